// round 8
// baseline (speedup 1.0000x reference)
#include <cuda_runtime.h>

#define IMG_W 200
#define CHAN 512
#define NF4  (CHAN / 4)
#define POOL 7
#define NROI 300

__constant__ int4 c_rois[NROI];

// grid = (49, 300). 128 threads, one float4 lane each.
// - ROI geometry read from __constant__ (const-cache hit, no L2 round-trip
//   at the head of each block's dependency chain).
// - Zero-weight corner loads skipped (block-uniform branches).
// - Streaming stores (__stcs): output is write-once, keep the image L2-resident.
__global__ void __launch_bounds__(128) roi_pool_kernel(
    const float* __restrict__ img,   // [200,200,512]
    float*       __restrict__ out)   // [300,7,7,512]
{
    const int gx  = blockIdx.x % POOL;
    const int gy  = blockIdx.x / POOL;
    const int roi = blockIdx.y;

    const int4 r = c_rois[roi];
    const int x0 = r.x, y0 = r.y, w = r.z, h = r.w;

    // Reference numerics.
    const float ys = (float)y0 + (float)gy * ((float)h / (float)POOL);
    const float xs = (float)x0 + (float)gx * ((float)w / (float)POOL);
    const int ty = (int)floorf(ys);
    const int tx = (int)floorf(xs);
    const float fy = ys - (float)ty;
    const float fx = xs - (float)tx;
    const int by = min(ty + 1, y0 + h - 1);
    const int bx = min(tx + 1, x0 + w - 1);

    const bool lx = (fx != 0.0f);
    const bool ly = (fy != 0.0f);

    const int c4 = threadIdx.x;
    const float4* __restrict__ base = (const float4*)img;

    const int o00 = (ty * IMG_W + tx) * NF4 + c4;
    const int o01 = (ty * IMG_W + bx) * NF4 + c4;
    const int o10 = (by * IMG_W + tx) * NF4 + c4;
    const int o11 = (by * IMG_W + bx) * NF4 + c4;

    const float4 zero = make_float4(0.f, 0.f, 0.f, 0.f);

    const float4 v00 = __ldg(base + o00);
    float4 v01 = zero, v10 = zero, v11 = zero;
    if (lx)       v01 = __ldg(base + o01);
    if (ly)       v10 = __ldg(base + o10);
    if (lx && ly) v11 = __ldg(base + o11);

    const float omfx = 1.0f - fx;
    const float omfy = 1.0f - fy;

    float4 res;
    res.x = omfy * (omfx * v00.x + fx * v01.x) + fy * (omfx * v10.x + fx * v11.x);
    res.y = omfy * (omfx * v00.y + fx * v01.y) + fy * (omfx * v10.y + fx * v11.y);
    res.z = omfy * (omfx * v00.z + fx * v01.z) + fy * (omfx * v10.z + fx * v11.z);
    res.w = omfy * (omfx * v00.w + fx * v01.w) + fy * (omfx * v10.w + fx * v11.w);

    const int opos = (roi * (POOL * POOL) + blockIdx.x) * NF4 + c4;
    __stcs(((float4*)out) + opos, res);
}

extern "C" void kernel_launch(void* const* d_in, const int* in_sizes, int n_in,
                              void* d_out, int out_size) {
    const float* img  = (const float*)d_in[0];
    const int*   rois = (const int*)d_in[1];
    float*       out  = (float*)d_out;

    // DtoD async copy into constant bank (graph-capturable, no allocation).
    cudaMemcpyToSymbolAsync(c_rois, rois, NROI * sizeof(int4), 0,
                            cudaMemcpyDeviceToDevice);

    dim3 grid(POOL * POOL, NROI);   // (49, 300)
    roi_pool_kernel<<<grid, 128>>>(img, out);
}

// round 9
// speedup vs baseline: 1.1400x; 1.1400x over previous
#include <cuda_runtime.h>

#define IMG_W 200
#define CHAN 512
#define NF4  (CHAN / 4)
#define POOL 7
#define NROI 300
#define NPOS (NROI * POOL * POOL)   // 14700

// One WARP per pool position; each warp processes all 4 channel chunks
// (lane + 32*i, i=0..3) with a depth-2 software pipeline of gathers.
// grid = 3675 blocks x 128 threads (4 warps = 4 positions per block).
__global__ void __launch_bounds__(128) roi_pool_warp_kernel(
    const float* __restrict__ img,   // [200,200,512]
    const int*   __restrict__ rois,  // [300,4] = (x,y,w,h)
    float*       __restrict__ out)   // [300,7,7,512]
{
    const int wid  = threadIdx.x >> 5;           // warp 0..3
    const int lane = threadIdx.x & 31;
    const int pos  = blockIdx.x * 4 + wid;       // 0..14699

    const int roi = pos / (POOL * POOL);
    const int pp  = pos % (POOL * POOL);
    const int gy  = pp / POOL;
    const int gx  = pp % POOL;

    const int4 r = __ldg((const int4*)rois + roi);
    const int x0 = r.x, y0 = r.y, w = r.z, h = r.w;

    // Reference numerics.
    const float ys = (float)y0 + (float)gy * ((float)h / (float)POOL);
    const float xs = (float)x0 + (float)gx * ((float)w / (float)POOL);
    const int ty = (int)floorf(ys);
    const int tx = (int)floorf(xs);
    const float fy = ys - (float)ty;
    const float fx = xs - (float)tx;
    const int by = min(ty + 1, y0 + h - 1);
    const int bx = min(tx + 1, x0 + w - 1);

    const bool lx = (fx != 0.0f);
    const bool ly = (fy != 0.0f);

    const float4* __restrict__ base = (const float4*)img;
    float4* __restrict__ out4 = (float4*)out;

    // Warp-uniform base offsets (float4 units); lane offset added per chunk.
    const int o00 = (ty * IMG_W + tx) * NF4 + lane;
    const int o01 = (ty * IMG_W + bx) * NF4 + lane;
    const int o10 = (by * IMG_W + tx) * NF4 + lane;
    const int o11 = (by * IMG_W + bx) * NF4 + lane;
    const int ob  = pos * NF4 + lane;

    const float omfx = 1.0f - fx;
    const float omfy = 1.0f - fy;
    const float4 zero = make_float4(0.f, 0.f, 0.f, 0.f);

    // Depth-2 pipeline over 4 chunks.
    float4 v00[2], v01[2], v10[2], v11[2];

    #define LOADC(i_, s_)                                              \
    do {                                                               \
        const int c_ = (i_) * 32;                                      \
        v00[s_] = __ldg(base + o00 + c_);                              \
        v01[s_] = lx ? __ldg(base + o01 + c_) : zero;                  \
        v10[s_] = ly ? __ldg(base + o10 + c_) : zero;                  \
        v11[s_] = (lx && ly) ? __ldg(base + o11 + c_) : zero;          \
    } while (0)

    LOADC(0, 0);
    LOADC(1, 1);

    #pragma unroll
    for (int i = 0; i < 4; i++) {
        const int s = i & 1;
        // Prefetch chunk i+2 into the slot we're about to free.
        // (Loads issued before consuming slot s of chunk i? No — slot s holds
        //  chunk i; issue i+2 AFTER consuming. Consume first, then prefetch.)
        const float4 a = v00[s], b = v01[s], c = v10[s], d = v11[s];
        if (i < 2) { /* chunks 2,3 prefetched below after consume */ }

        float4 res;
        res.x = omfy * (omfx * a.x + fx * b.x) + fy * (omfx * c.x + fx * d.x);
        res.y = omfy * (omfx * a.y + fx * b.y) + fy * (omfx * c.y + fx * d.y);
        res.z = omfy * (omfx * a.z + fx * b.z) + fy * (omfx * c.z + fx * d.z);
        res.w = omfy * (omfx * a.w + fx * b.w) + fy * (omfx * c.w + fx * d.w);

        out4[ob + i * 32] = res;

        if (i + 2 < 4) LOADC(i + 2, s);
    }
    #undef LOADC
}

extern "C" void kernel_launch(void* const* d_in, const int* in_sizes, int n_in,
                              void* d_out, int out_size) {
    const float* img  = (const float*)d_in[0];
    const int*   rois = (const int*)d_in[1];
    float*       out  = (float*)d_out;

    roi_pool_warp_kernel<<<NPOS / 4, 128>>>(img, rois, out);
}